// round 16
// baseline (speedup 1.0000x reference)
#include <cuda_runtime.h>
#include <cuda_fp16.h>
#include <math.h>
#include <stdint.h>

// Problem constants
#define BATCH  4
#define SEQ    2048
#define DMODEL 1024
#define NHEAD  16
#define HD     64
#define MTOT   (BATCH * SEQ)   // 8192

// Scratch (allocation-free: __device__ globals) — fp16 activations/weights
__device__ __half g_qkv[(size_t)BATCH * SEQ * 3 * DMODEL];  // [B,T,3D]
__device__ __half g_y  [(size_t)BATCH * SEQ * DMODEL];      // [B,T,D]
__device__ __half g_x  [(size_t)MTOT * DMODEL];
__device__ __half g_wq [(size_t)DMODEL * 3 * DMODEL];
__device__ __half g_wp [(size_t)DMODEL * DMODEL];

// ---------------------------------------------------------------------------
// Helpers
// ---------------------------------------------------------------------------
// NOTE: non-volatile — pure register op, outputs always consumed. Lets ptxas
// interleave MMAs with later (volatile) LDSMs to hide LDS latency.
__device__ __forceinline__ void mma16(float* c, const uint32_t* a,
                                      uint32_t b0, uint32_t b1) {
    asm("mma.sync.aligned.m16n8k16.row.col.f32.f16.f16.f32 "
        "{%0,%1,%2,%3},{%4,%5,%6,%7},{%8,%9},{%0,%1,%2,%3};\n"
        : "+f"(c[0]), "+f"(c[1]), "+f"(c[2]), "+f"(c[3])
        : "r"(a[0]), "r"(a[1]), "r"(a[2]), "r"(a[3]), "r"(b0), "r"(b1));
}
__device__ __forceinline__ void ldsm4(uint32_t& r0, uint32_t& r1,
                                      uint32_t& r2, uint32_t& r3, uint32_t a) {
    asm volatile("ldmatrix.sync.aligned.m8n8.x4.shared.b16 {%0,%1,%2,%3}, [%4];"
                 : "=r"(r0), "=r"(r1), "=r"(r2), "=r"(r3) : "r"(a));
}
__device__ __forceinline__ void ldsm4t(uint32_t& r0, uint32_t& r1,
                                       uint32_t& r2, uint32_t& r3, uint32_t a) {
    asm volatile("ldmatrix.sync.aligned.m8n8.x4.trans.shared.b16 {%0,%1,%2,%3}, [%4];"
                 : "=r"(r0), "=r"(r1), "=r"(r2), "=r"(r3) : "r"(a));
}
__device__ __forceinline__ void cp_async16(uint32_t smem_dst, const void* gsrc) {
    asm volatile("cp.async.cg.shared.global [%0], [%1], 16;\n"
                 :: "r"(smem_dst), "l"(gsrc));
}
__device__ __forceinline__ void cp_commit() {
    asm volatile("cp.async.commit_group;\n");
}
template <int N>
__device__ __forceinline__ void cp_wait() {
    asm volatile("cp.async.wait_group %0;\n" :: "n"(N));
}
__device__ __forceinline__ float fast_ex2(float x) {
    float r;
    asm("ex2.approx.f32 %0, %1;" : "=f"(r) : "f"(x));
    return r;
}
// Packed half2 exp2: one MUFU op for two values; result IS fp16 P.
__device__ __forceinline__ uint32_t ex2_h2(float a, float b) {
    __half2 h = __floats2half2_rn(a, b);
    uint32_t u = *reinterpret_cast<uint32_t*>(&h);
    uint32_t r;
    asm("ex2.approx.f16x2 %0, %1;" : "=r"(r) : "r"(u));
    return r;
}

// ---------------------------------------------------------------------------
// Fused fp32 -> fp16 convert for all three tensors (one launch)
// ---------------------------------------------------------------------------
__global__ void to_half3(const float* __restrict__ a, __half* __restrict__ oa, int na4,
                         const float* __restrict__ b, __half* __restrict__ ob, int nb4,
                         const float* __restrict__ c, __half* __restrict__ oc, int nc4)
{
    int i = blockIdx.x * blockDim.x + threadIdx.x;
    const float* src;
    __half* dst;
    int idx;
    if (i < na4)            { src = a; dst = oa; idx = i; }
    else if (i < na4 + nb4) { src = b; dst = ob; idx = i - na4; }
    else if (i < na4 + nb4 + nc4) { src = c; dst = oc; idx = i - na4 - nb4; }
    else return;
    float4 v = ((const float4*)src)[idx];
    __half2* o = (__half2*)dst + 2 * (size_t)idx;
    o[0] = __floats2half2_rn(v.x, v.y);
    o[1] = __floats2half2_rn(v.z, v.w);
}

// ---------------------------------------------------------------------------
// fp16 tensor-core GEMM + bias. BM=BN=128, BK=64 (halved barrier count),
// 8 warps (2x4), warp tile 64x32, m16n8k16, 3-stage cp.async ring,
// 2 CTAs/SM. A rows 72 halfs (144B), B rows 136 halfs (272B):
// both stride%128B = 16 -> conflict-free LDSM phases.
// ---------------------------------------------------------------------------
#define AS2 72
#define BS2 136
#define G_STAGES 3
#define A_STGH (128 * AS2)       // halfs per A stage (9216)
#define B_STGH (64 * BS2)        // halfs per B stage (8704)
#define GEMM_SMEM ((G_STAGES * (A_STGH + B_STGH)) * 2)   // 107520 B

template <bool HALF_OUT>
__global__ void __launch_bounds__(256, 2)
gemm_fp16(int M, int N, int K,
          const __half* __restrict__ A,
          const __half* __restrict__ W,
          const float* __restrict__ bias,
          void* __restrict__ Cv)
{
    extern __shared__ __half dsm[];
    __half* As = dsm;
    __half* Bs = dsm + G_STAGES * A_STGH;
    const uint32_t as_u32 = (uint32_t)__cvta_generic_to_shared(As);
    const uint32_t bs_u32 = (uint32_t)__cvta_generic_to_shared(Bs);

    const int tid  = threadIdx.x;
    const int wid  = tid >> 5;
    const int lane = tid & 31;
    const int gid  = lane >> 2;
    const int tig  = lane & 3;
    const int wm   = wid >> 2;   // 0..1 -> 64 rows
    const int wn   = wid & 3;    // 0..3 -> 32 cols

    const __half* Ab = A + (size_t)blockIdx.y * 128 * K;
    const __half* Wb = W + (size_t)blockIdx.x * 128;

    // cp.async maps (256 threads): A 128 rows x 8 chunks, B 64 rows x 16 chunks
    const int aRow = tid >> 1;              // 0..127
    const int aC0  = (tid & 1) * 4;         // chunks 0..3 / 4..7
    const int bRow = tid >> 2;              // 0..63
    const int bC0  = (tid & 3) * 4;         // chunks 0,4,8,12

    // ldmatrix lane components
    const int j    = lane >> 3;             // matrix idx 0..3
    const int l7   = lane & 7;
    const int aLr  = (j & 1) * 8 + l7;      // A row-style
    const int aLc  = (j >> 1) * 8;
    const int bLk  = (j & 1) * 8 + l7;      // B trans k-row
    const int bLn  = (j >> 1) * 8;

    float c[4][4][4];
    #pragma unroll
    for (int i = 0; i < 4; i++)
        #pragma unroll
        for (int jj = 0; jj < 4; jj++)
            #pragma unroll
            for (int r = 0; r < 4; r++) c[i][jj][r] = 0.0f;

    const int T = K / 64;   // 16

    auto issue = [&](int kt, int s) {
        uint32_t ad = as_u32 + (uint32_t)(s * A_STGH + aRow * AS2) * 2;
        const __half* asrc = Ab + (size_t)aRow * K + kt * 64;
        #pragma unroll
        for (int i = 0; i < 4; i++)
            cp_async16(ad + (aC0 + i) * 16, asrc + (aC0 + i) * 8);
        uint32_t bd = bs_u32 + (uint32_t)(s * B_STGH + bRow * BS2) * 2;
        const __half* bsrc = Wb + (size_t)(kt * 64 + bRow) * N;
        #pragma unroll
        for (int i = 0; i < 4; i++)
            cp_async16(bd + (bC0 + i) * 16, bsrc + (bC0 + i) * 8);
        cp_commit();
    };

    issue(0, 0);
    issue(1, 1);

    int cs = 0;   // compute slot for tile t
    int is = 2;   // issue slot for tile t+2
    for (int t = 0; t < T; t++) {
        if (t + 1 < T) cp_wait<1>(); else cp_wait<0>();
        __syncthreads();
        if (t + 2 < T) issue(t + 2, is);

        const uint32_t abase = as_u32 + (uint32_t)(cs * A_STGH) * 2;
        const uint32_t bbase = bs_u32 + (uint32_t)(cs * B_STGH) * 2;

        #pragma unroll
        for (int kk = 0; kk < 64; kk += 16) {
            uint32_t a[4][4];
            #pragma unroll
            for (int mt = 0; mt < 4; mt++) {
                uint32_t ad = abase +
                    (uint32_t)((wm * 64 + mt * 16 + aLr) * AS2 + kk + aLc) * 2;
                ldsm4(a[mt][0], a[mt][1], a[mt][2], a[mt][3], ad);
            }
            uint32_t bg[2][4];
            #pragma unroll
            for (int g = 0; g < 2; g++) {
                uint32_t bd = bbase +
                    (uint32_t)((kk + bLk) * BS2 + wn * 32 + g * 16 + bLn) * 2;
                ldsm4t(bg[g][0], bg[g][1], bg[g][2], bg[g][3], bd);
            }
            #pragma unroll
            for (int mt = 0; mt < 4; mt++)
                #pragma unroll
                for (int g = 0; g < 2; g++) {
                    mma16(c[mt][2 * g],     a[mt], bg[g][0], bg[g][1]);
                    mma16(c[mt][2 * g + 1], a[mt], bg[g][2], bg[g][3]);
                }
        }
        cs = (cs == 2) ? 0 : cs + 1;
        is = (is == 2) ? 0 : is + 1;
    }

    // Epilogue
    #pragma unroll
    for (int mt = 0; mt < 4; mt++) {
        const int r = blockIdx.y * 128 + wm * 64 + mt * 16 + gid;
        #pragma unroll
        for (int nt = 0; nt < 4; nt++) {
            const int col = blockIdx.x * 128 + wn * 32 + nt * 8 + 2 * tig;
            float2 bv = *(const float2*)&bias[col];
            if (HALF_OUT) {
                __half* C = (__half*)Cv;
                *(__half2*)&C[(size_t)(r    ) * N + col] =
                    __floats2half2_rn(c[mt][nt][0] + bv.x, c[mt][nt][1] + bv.y);
                *(__half2*)&C[(size_t)(r + 8) * N + col] =
                    __floats2half2_rn(c[mt][nt][2] + bv.x, c[mt][nt][3] + bv.y);
            } else {
                float* C = (float*)Cv;
                float2 o0, o1;
                o0.x = c[mt][nt][0] + bv.x; o0.y = c[mt][nt][1] + bv.y;
                o1.x = c[mt][nt][2] + bv.x; o1.y = c[mt][nt][3] + bv.y;
                *(float2*)&C[(size_t)(r    ) * N + col] = o0;
                *(float2*)&C[(size_t)(r + 8) * N + col] = o1;
            }
        }
    }
}

// ---------------------------------------------------------------------------
// fp16 tensor-core flash attention — 256 threads, 8 warps x 16 q-rows
// (Br=128, Bc=64), occupancy 2 => 16 warps/SM.
// m16n8k16, cp.async double-buffered K/V, dynamic smem 54KB.
// Base-2 softmax with ex2.approx.f16x2 (result IS fp16 P, stored directly).
// Layout: K[2][64*AT_S] | V[2][64*AT_S] | PQ[128*AT_S]
// ---------------------------------------------------------------------------
#define AT_S 72   // halfs per row (144B; %128B == 16 -> conflict-free)
#define KV_STGH (64 * AT_S)
#define ATTN_SMEM ((4 * KV_STGH + 128 * AT_S) * 2)   // 55296 B
#define SCALE_LOG2E 0.1803368801111244f   // 0.125 * log2(e)

__global__ void __launch_bounds__(256, 2)
attn_fp16(const __half* __restrict__ qkv, __half* __restrict__ y)
{
    extern __shared__ __half asm_[];
    __half* Ksm = asm_;
    __half* Vsm = asm_ + 2 * KV_STGH;
    __half* Pq  = asm_ + 4 * KV_STGH;
    const uint32_t k_u32 = (uint32_t)__cvta_generic_to_shared(Ksm);
    const uint32_t v_u32 = (uint32_t)__cvta_generic_to_shared(Vsm);
    const uint32_t p_u32 = (uint32_t)__cvta_generic_to_shared(Pq);

    const int b    = blockIdx.z;
    const int h    = blockIdx.y;
    const int q0   = blockIdx.x * 128;
    const int tid  = threadIdx.x;
    const int wid  = tid >> 5;          // 0..7 -> 16 q-rows each
    const int lane = tid & 31;
    const int gid  = lane >> 2;
    const int tig  = lane & 3;
    const int pr   = wid * 16 + gid;    // this thread's q-row (frag row 0)

    // cp.async maps (256 threads)
    const int qRow = tid >> 1;          // Q rows 0..127, 4 chunks each
    const int qC0  = (tid & 1) * 4;
    const int sRow = tid >> 2;          // K/V rows 0..63, 2 chunks each
    const int sC0  = (tid & 3) * 2;

    // ldmatrix lane components
    const int j   = lane >> 3;
    const int l7  = lane & 7;
    const int aLr = (j & 1) * 8 + l7;   // A-style (Q/P) row
    const int aLc = (j >> 1) * 8;
    const int nLr = (j >> 1) * 8 + l7;  // K non-trans n-row
    const int nLc = (j & 1) * 8;
    const int vLk = (j & 1) * 8 + l7;   // V trans key-row
    const int vLn = (j >> 1) * 8;

    auto issue_q = [&]() {
        const __half* src = qkv + ((size_t)(b * SEQ + q0 + qRow)) * (3 * DMODEL)
                          + h * HD;
        uint32_t qd = p_u32 + (uint32_t)(qRow * AT_S) * 2;
        #pragma unroll
        for (int i = 0; i < 4; i++)
            cp_async16(qd + (qC0 + i) * 16, src + (qC0 + i) * 8);
        cp_commit();
    };
    auto issue_kv = [&](int kt, int s) {
        const __half* src = qkv + ((size_t)(b * SEQ + kt + sRow)) * (3 * DMODEL)
                          + DMODEL + h * HD;
        uint32_t kd = k_u32 + (uint32_t)(s * KV_STGH + sRow * AT_S) * 2;
        uint32_t vd = v_u32 + (uint32_t)(s * KV_STGH + sRow * AT_S) * 2;
        #pragma unroll
        for (int i = 0; i < 2; i++) {
            cp_async16(kd + (sC0 + i) * 16, src + (sC0 + i) * 8);
            cp_async16(vd + (sC0 + i) * 16, src + DMODEL + (sC0 + i) * 8);
        }
        cp_commit();
    };

    issue_q();
    issue_kv(0, 0);
    cp_wait<0>();
    __syncthreads();

    // Q fragments resident (4 k16 slabs)
    uint32_t qa[4][4];
    #pragma unroll
    for (int sl = 0; sl < 4; sl++) {
        uint32_t ad = p_u32 +
            (uint32_t)((wid * 16 + aLr) * AT_S + sl * 16 + aLc) * 2;
        ldsm4(qa[sl][0], qa[sl][1], qa[sl][2], qa[sl][3], ad);
    }

    float o[8][4];
    #pragma unroll
    for (int n = 0; n < 8; n++)
        #pragma unroll
        for (int q = 0; q < 4; q++) o[n][q] = 0.0f;
    float m0 = -1e30f, m1 = -1e30f, l0 = 0.0f, l1 = 0.0f;

    const int NT = SEQ / 64;
    for (int t = 0; t < NT; t++) {
        if (t > 0) {
            cp_wait<0>();
            __syncthreads();
        }
        if (t + 1 < NT) issue_kv((t + 1) * 64, (t + 1) & 1);

        const uint32_t kb = k_u32 + (uint32_t)((t & 1) * KV_STGH) * 2;
        const uint32_t vb = v_u32 + (uint32_t)((t & 1) * KV_STGH) * 2;

        // ---- S = Q K^T ----
        float s[8][4];
        #pragma unroll
        for (int n = 0; n < 8; n++)
            #pragma unroll
            for (int q = 0; q < 4; q++) s[n][q] = 0.0f;
        #pragma unroll
        for (int sl = 0; sl < 4; sl++) {
            const int kk = sl * 16;
            #pragma unroll
            for (int g = 0; g < 4; g++) {
                uint32_t r0, r1, r2, r3;
                uint32_t kd = kb + (uint32_t)((g * 16 + nLr) * AT_S + kk + nLc) * 2;
                ldsm4(r0, r1, r2, r3, kd);
                mma16(s[2 * g],     qa[sl], r0, r1);
                mma16(s[2 * g + 1], qa[sl], r2, r3);
            }
        }

        // ---- online softmax (base-2, f16x2 exp), rows pr and pr+8 ----
        float mx0 = -1e30f, mx1 = -1e30f;
        #pragma unroll
        for (int n = 0; n < 8; n++) {
            s[n][0] *= SCALE_LOG2E; s[n][1] *= SCALE_LOG2E;
            s[n][2] *= SCALE_LOG2E; s[n][3] *= SCALE_LOG2E;
            mx0 = fmaxf(mx0, fmaxf(s[n][0], s[n][1]));
            mx1 = fmaxf(mx1, fmaxf(s[n][2], s[n][3]));
        }
        mx0 = fmaxf(mx0, __shfl_xor_sync(0xffffffffu, mx0, 1));
        mx0 = fmaxf(mx0, __shfl_xor_sync(0xffffffffu, mx0, 2));
        mx1 = fmaxf(mx1, __shfl_xor_sync(0xffffffffu, mx1, 1));
        mx1 = fmaxf(mx1, __shfl_xor_sync(0xffffffffu, mx1, 2));
        const float mn0 = fmaxf(m0, mx0);
        const float mn1 = fmaxf(m1, mx1);
        const float al0 = fast_ex2(m0 - mn0);
        const float al1 = fast_ex2(m1 - mn1);
        m0 = mn0; m1 = mn1;

        // exp2 in packed fp16; result IS fp16 P -> store directly
        float sum0 = 0.0f, sum1 = 0.0f;
        #pragma unroll
        for (int n = 0; n < 8; n++) {
            uint32_t p0 = ex2_h2(s[n][0] - mn0, s[n][1] - mn0);
            uint32_t p1 = ex2_h2(s[n][2] - mn1, s[n][3] - mn1);
            *(uint32_t*)&Pq[(pr    ) * AT_S + n * 8 + 2 * tig] = p0;
            *(uint32_t*)&Pq[(pr + 8) * AT_S + n * 8 + 2 * tig] = p1;
            float2 f0 = __half22float2(*reinterpret_cast<__half2*>(&p0));
            float2 f1 = __half22float2(*reinterpret_cast<__half2*>(&p1));
            sum0 += f0.x + f0.y;
            sum1 += f1.x + f1.y;
        }
        sum0 += __shfl_xor_sync(0xffffffffu, sum0, 1);
        sum0 += __shfl_xor_sync(0xffffffffu, sum0, 2);
        sum1 += __shfl_xor_sync(0xffffffffu, sum1, 1);
        sum1 += __shfl_xor_sync(0xffffffffu, sum1, 2);
        l0 = l0 * al0 + sum0;
        l1 = l1 * al1 + sum1;

        #pragma unroll
        for (int n = 0; n < 8; n++) {
            o[n][0] *= al0; o[n][1] *= al0;
            o[n][2] *= al1; o[n][3] *= al1;
        }
        __syncwarp();

        // ---- O += P @ V ----
        #pragma unroll
        for (int sl = 0; sl < 4; sl++) {
            const int kk = sl * 16;
            uint32_t pa[4];
            {
                uint32_t pd = p_u32 +
                    (uint32_t)((wid * 16 + aLr) * AT_S + kk + aLc) * 2;
                ldsm4(pa[0], pa[1], pa[2], pa[3], pd);
            }
            #pragma unroll
            for (int g = 0; g < 4; g++) {
                uint32_t r0, r1, r2, r3;
                uint32_t vd = vb + (uint32_t)((kk + vLk) * AT_S + g * 16 + vLn) * 2;
                ldsm4t(r0, r1, r2, r3, vd);
                mma16(o[2 * g],     pa, r0, r1);
                mma16(o[2 * g + 1], pa, r2, r3);
            }
        }
    }

    // ---- normalize + write y (fp16) ----
    const float i0 = 1.0f / l0;
    const float i1 = 1.0f / l1;
    __half* yp = y + ((size_t)(b * SEQ + q0 + pr)) * DMODEL + h * HD;
    #pragma unroll
    for (int n = 0; n < 8; n++) {
        const int cc = n * 8 + 2 * tig;
        *(__half2*)&yp[cc] = __floats2half2_rn(o[n][0] * i0, o[n][1] * i0);
        *(__half2*)&yp[8 * DMODEL + cc] =
            __floats2half2_rn(o[n][2] * i1, o[n][3] * i1);
    }
}

// ---------------------------------------------------------------------------
// Launch
// ---------------------------------------------------------------------------
extern "C" void kernel_launch(void* const* d_in, const int* in_sizes, int n_in,
                              void* d_out, int out_size)
{
    const float* x     = (const float*)d_in[0];
    const float* Wqkv  = (const float*)d_in[1];
    const float* bqkv  = (const float*)d_in[2];
    const float* Wproj = (const float*)d_in[3];
    const float* bproj = (const float*)d_in[4];
    float* out = (float*)d_out;

    __half *qkv = nullptr, *y = nullptr, *xh = nullptr, *wq = nullptr, *wp = nullptr;
    cudaGetSymbolAddress((void**)&qkv, g_qkv);
    cudaGetSymbolAddress((void**)&y,   g_y);
    cudaGetSymbolAddress((void**)&xh,  g_x);
    cudaGetSymbolAddress((void**)&wq,  g_wq);
    cudaGetSymbolAddress((void**)&wp,  g_wp);

    cudaFuncSetAttribute(gemm_fp16<true>,
                         cudaFuncAttributeMaxDynamicSharedMemorySize, GEMM_SMEM);
    cudaFuncSetAttribute(gemm_fp16<false>,
                         cudaFuncAttributeMaxDynamicSharedMemorySize, GEMM_SMEM);
    cudaFuncSetAttribute(attn_fp16,
                         cudaFuncAttributeMaxDynamicSharedMemorySize, ATTN_SMEM);

    // 0) convert inputs/weights to fp16 (single fused launch)
    {
        const int na4 = MTOT * DMODEL / 4;           // x
        const int nb4 = DMODEL * 3 * DMODEL / 4;     // Wqkv
        const int nc4 = DMODEL * DMODEL / 4;         // Wproj
        const int tot = na4 + nb4 + nc4;
        to_half3<<<(tot + 255) / 256, 256>>>(x, xh, na4, Wqkv, wq, nb4,
                                             Wproj, wp, nc4);
    }

    // 1) QKV projection -> fp16 qkv
    gemm_fp16<true><<<dim3(3 * DMODEL / 128, MTOT / 128), 256, GEMM_SMEM>>>(
        MTOT, 3 * DMODEL, DMODEL, xh, wq, bqkv, qkv);

    // 2) flash attention -> fp16 y  (256 threads, Br=128)
    attn_fp16<<<dim3(SEQ / 128, NHEAD, BATCH), 256, ATTN_SMEM>>>(qkv, y);

    // 3) output projection -> fp32 out
    gemm_fp16<false><<<dim3(DMODEL / 128, MTOT / 128), 256, GEMM_SMEM>>>(
        MTOT, DMODEL, DMODEL, y, wp, bproj, out);
}

// round 17
// speedup vs baseline: 1.6782x; 1.6782x over previous
#include <cuda_runtime.h>
#include <cuda_fp16.h>
#include <math.h>
#include <stdint.h>

// Problem constants
#define BATCH  4
#define SEQ    2048
#define DMODEL 1024
#define NHEAD  16
#define HD     64
#define MTOT   (BATCH * SEQ)   // 8192

// Scratch (allocation-free: __device__ globals) — fp16 activations/weights
__device__ __half g_qkv[(size_t)BATCH * SEQ * 3 * DMODEL];  // [B,T,3D]
__device__ __half g_y  [(size_t)BATCH * SEQ * DMODEL];      // [B,T,D]
__device__ __half g_x  [(size_t)MTOT * DMODEL];
__device__ __half g_wq [(size_t)DMODEL * 3 * DMODEL];
__device__ __half g_wp [(size_t)DMODEL * DMODEL];

// ---------------------------------------------------------------------------
// Helpers  (mma16 back to volatile — the measured-524us configuration)
// ---------------------------------------------------------------------------
__device__ __forceinline__ void mma16(float* c, const uint32_t* a,
                                      uint32_t b0, uint32_t b1) {
    asm volatile(
        "mma.sync.aligned.m16n8k16.row.col.f32.f16.f16.f32 "
        "{%0,%1,%2,%3},{%4,%5,%6,%7},{%8,%9},{%0,%1,%2,%3};\n"
        : "+f"(c[0]), "+f"(c[1]), "+f"(c[2]), "+f"(c[3])
        : "r"(a[0]), "r"(a[1]), "r"(a[2]), "r"(a[3]), "r"(b0), "r"(b1));
}
__device__ __forceinline__ void ldsm4(uint32_t& r0, uint32_t& r1,
                                      uint32_t& r2, uint32_t& r3, uint32_t a) {
    asm volatile("ldmatrix.sync.aligned.m8n8.x4.shared.b16 {%0,%1,%2,%3}, [%4];"
                 : "=r"(r0), "=r"(r1), "=r"(r2), "=r"(r3) : "r"(a));
}
__device__ __forceinline__ void ldsm4t(uint32_t& r0, uint32_t& r1,
                                       uint32_t& r2, uint32_t& r3, uint32_t a) {
    asm volatile("ldmatrix.sync.aligned.m8n8.x4.trans.shared.b16 {%0,%1,%2,%3}, [%4];"
                 : "=r"(r0), "=r"(r1), "=r"(r2), "=r"(r3) : "r"(a));
}
__device__ __forceinline__ void cp_async16(uint32_t smem_dst, const void* gsrc) {
    asm volatile("cp.async.cg.shared.global [%0], [%1], 16;\n"
                 :: "r"(smem_dst), "l"(gsrc));
}
__device__ __forceinline__ void cp_commit() {
    asm volatile("cp.async.commit_group;\n");
}
template <int N>
__device__ __forceinline__ void cp_wait() {
    asm volatile("cp.async.wait_group %0;\n" :: "n"(N));
}
__device__ __forceinline__ float fast_ex2(float x) {
    float r;
    asm("ex2.approx.f32 %0, %1;" : "=f"(r) : "f"(x));
    return r;
}
// Packed half2 exp2: one MUFU op for two values; result IS fp16 P.
__device__ __forceinline__ uint32_t ex2_h2(float a, float b) {
    __half2 h = __floats2half2_rn(a, b);
    uint32_t u = *reinterpret_cast<uint32_t*>(&h);
    uint32_t r;
    asm("ex2.approx.f16x2 %0, %1;" : "=r"(r) : "r"(u));
    return r;
}

// ---------------------------------------------------------------------------
// Fused fp32 -> fp16 convert for all three tensors (one launch)
// ---------------------------------------------------------------------------
__global__ void to_half3(const float* __restrict__ a, __half* __restrict__ oa, int na4,
                         const float* __restrict__ b, __half* __restrict__ ob, int nb4,
                         const float* __restrict__ c, __half* __restrict__ oc, int nc4)
{
    int i = blockIdx.x * blockDim.x + threadIdx.x;
    const float* src;
    __half* dst;
    int idx;
    if (i < na4)            { src = a; dst = oa; idx = i; }
    else if (i < na4 + nb4) { src = b; dst = ob; idx = i - na4; }
    else if (i < na4 + nb4 + nc4) { src = c; dst = oc; idx = i - na4 - nb4; }
    else return;
    float4 v = ((const float4*)src)[idx];
    __half2* o = (__half2*)dst + 2 * (size_t)idx;
    o[0] = __floats2half2_rn(v.x, v.y);
    o[1] = __floats2half2_rn(v.z, v.w);
}

// ---------------------------------------------------------------------------
// fp16 tensor-core GEMM + bias. BM=BN=128, BK=32, 8 warps (2x4),
// warp tile 64x32, m16n8k16, 4-stage cp.async ring (&3 slots), 2 CTAs/SM.
// (EXACT round-15 configuration — measured 192us QKV / 44% tensor.)
// ---------------------------------------------------------------------------
#define AS2 40
#define BS2 136
#define G_STAGES 4
#define A_STGH (128 * AS2)       // halfs per A stage (5120)
#define B_STGH (32 * BS2)        // halfs per B stage (4352)
#define GEMM_SMEM ((G_STAGES * (A_STGH + B_STGH)) * 2)   // 75776 B

template <bool HALF_OUT>
__global__ void __launch_bounds__(256, 2)
gemm_fp16(int M, int N, int K,
          const __half* __restrict__ A,
          const __half* __restrict__ W,
          const float* __restrict__ bias,
          void* __restrict__ Cv)
{
    extern __shared__ __half dsm[];
    __half* As = dsm;
    __half* Bs = dsm + G_STAGES * A_STGH;
    const uint32_t as_u32 = (uint32_t)__cvta_generic_to_shared(As);
    const uint32_t bs_u32 = (uint32_t)__cvta_generic_to_shared(Bs);

    const int tid  = threadIdx.x;
    const int wid  = tid >> 5;
    const int lane = tid & 31;
    const int gid  = lane >> 2;
    const int tig  = lane & 3;
    const int wm   = wid >> 2;   // 0..1 -> 64 rows
    const int wn   = wid & 3;    // 0..3 -> 32 cols

    const __half* Ab = A + (size_t)blockIdx.y * 128 * K;
    const __half* Wb = W + (size_t)blockIdx.x * 128;

    const int aRow = tid >> 1;              // 0..127
    const int aC0  = (tid & 1) * 2;         // chunk 0..3 (16B each)
    const int bRow = tid >> 3;              // 0..31
    const int bC0  = (tid & 7) * 2;         // chunk 0..15

    const int j    = lane >> 3;             // matrix idx 0..3
    const int l7   = lane & 7;
    const int aLr  = (j & 1) * 8 + l7;      // A row-style
    const int aLc  = (j >> 1) * 8;
    const int bLk  = (j & 1) * 8 + l7;      // B trans k-row
    const int bLn  = (j >> 1) * 8;

    float c[4][4][4];
    #pragma unroll
    for (int i = 0; i < 4; i++)
        #pragma unroll
        for (int jj = 0; jj < 4; jj++)
            #pragma unroll
            for (int r = 0; r < 4; r++) c[i][jj][r] = 0.0f;

    const int T = K / 32;

    auto issue = [&](int kt, int s) {
        uint32_t ad = as_u32 + (uint32_t)(s * A_STGH + aRow * AS2) * 2;
        const __half* asrc = Ab + (size_t)aRow * K + kt * 32;
        #pragma unroll
        for (int i = 0; i < 2; i++)
            cp_async16(ad + (aC0 + i) * 16, asrc + (aC0 + i) * 8);
        uint32_t bd = bs_u32 + (uint32_t)(s * B_STGH + bRow * BS2) * 2;
        const __half* bsrc = Wb + (size_t)(kt * 32 + bRow) * N;
        #pragma unroll
        for (int i = 0; i < 2; i++)
            cp_async16(bd + (bC0 + i) * 16, bsrc + (bC0 + i) * 8);
        cp_commit();
    };

    issue(0, 0);
    issue(1, 1);
    issue(2, 2);

    for (int t = 0; t < T; t++) {
        if (t + 2 < T)      cp_wait<2>();
        else if (t + 1 < T) cp_wait<1>();
        else                cp_wait<0>();
        __syncthreads();
        if (t + 3 < T) issue(t + 3, (t + 3) & 3);

        const uint32_t abase = as_u32 + (uint32_t)((t & 3) * A_STGH) * 2;
        const uint32_t bbase = bs_u32 + (uint32_t)((t & 3) * B_STGH) * 2;

        #pragma unroll
        for (int kk = 0; kk < 32; kk += 16) {
            uint32_t a[4][4];
            #pragma unroll
            for (int mt = 0; mt < 4; mt++) {
                uint32_t ad = abase +
                    (uint32_t)((wm * 64 + mt * 16 + aLr) * AS2 + kk + aLc) * 2;
                ldsm4(a[mt][0], a[mt][1], a[mt][2], a[mt][3], ad);
            }
            uint32_t bg[2][4];
            #pragma unroll
            for (int g = 0; g < 2; g++) {
                uint32_t bd = bbase +
                    (uint32_t)((kk + bLk) * BS2 + wn * 32 + g * 16 + bLn) * 2;
                ldsm4t(bg[g][0], bg[g][1], bg[g][2], bg[g][3], bd);
            }
            #pragma unroll
            for (int mt = 0; mt < 4; mt++)
                #pragma unroll
                for (int g = 0; g < 2; g++) {
                    mma16(c[mt][2 * g],     a[mt], bg[g][0], bg[g][1]);
                    mma16(c[mt][2 * g + 1], a[mt], bg[g][2], bg[g][3]);
                }
        }
    }

    // Epilogue
    #pragma unroll
    for (int mt = 0; mt < 4; mt++) {
        const int r = blockIdx.y * 128 + wm * 64 + mt * 16 + gid;
        #pragma unroll
        for (int nt = 0; nt < 4; nt++) {
            const int col = blockIdx.x * 128 + wn * 32 + nt * 8 + 2 * tig;
            float2 bv = *(const float2*)&bias[col];
            if (HALF_OUT) {
                __half* C = (__half*)Cv;
                *(__half2*)&C[(size_t)(r    ) * N + col] =
                    __floats2half2_rn(c[mt][nt][0] + bv.x, c[mt][nt][1] + bv.y);
                *(__half2*)&C[(size_t)(r + 8) * N + col] =
                    __floats2half2_rn(c[mt][nt][2] + bv.x, c[mt][nt][3] + bv.y);
            } else {
                float* C = (float*)Cv;
                float2 o0, o1;
                o0.x = c[mt][nt][0] + bv.x; o0.y = c[mt][nt][1] + bv.y;
                o1.x = c[mt][nt][2] + bv.x; o1.y = c[mt][nt][3] + bv.y;
                *(float2*)&C[(size_t)(r    ) * N + col] = o0;
                *(float2*)&C[(size_t)(r + 8) * N + col] = o1;
            }
        }
    }
}

// ---------------------------------------------------------------------------
// fp16 tensor-core flash attention — 256 threads, 8 warps x 16 q-rows
// (Br=128, Bc=64), occupancy 2 => 16 warps/SM.  (EXACT round-15 config.)
// m16n8k16, cp.async double-buffered K/V, dynamic smem 54KB.
// Base-2 softmax with ex2.approx.f16x2 (result IS fp16 P, stored directly).
// Layout: K[2][64*AT_S] | V[2][64*AT_S] | PQ[128*AT_S]
// ---------------------------------------------------------------------------
#define AT_S 72   // halfs per row (144B; %128B == 16 -> conflict-free)
#define KV_STGH (64 * AT_S)
#define ATTN_SMEM ((4 * KV_STGH + 128 * AT_S) * 2)   // 55296 B
#define SCALE_LOG2E 0.1803368801111244f   // 0.125 * log2(e)

__global__ void __launch_bounds__(256, 2)
attn_fp16(const __half* __restrict__ qkv, __half* __restrict__ y)
{
    extern __shared__ __half asm_[];
    __half* Ksm = asm_;
    __half* Vsm = asm_ + 2 * KV_STGH;
    __half* Pq  = asm_ + 4 * KV_STGH;
    const uint32_t k_u32 = (uint32_t)__cvta_generic_to_shared(Ksm);
    const uint32_t v_u32 = (uint32_t)__cvta_generic_to_shared(Vsm);
    const uint32_t p_u32 = (uint32_t)__cvta_generic_to_shared(Pq);

    const int b    = blockIdx.z;
    const int h    = blockIdx.y;
    const int q0   = blockIdx.x * 128;
    const int tid  = threadIdx.x;
    const int wid  = tid >> 5;          // 0..7 -> 16 q-rows each
    const int lane = tid & 31;
    const int gid  = lane >> 2;
    const int tig  = lane & 3;
    const int pr   = wid * 16 + gid;    // this thread's q-row (frag row 0)

    // cp.async maps (256 threads)
    const int qRow = tid >> 1;          // Q rows 0..127, 4 chunks each
    const int qC0  = (tid & 1) * 4;
    const int sRow = tid >> 2;          // K/V rows 0..63, 2 chunks each
    const int sC0  = (tid & 3) * 2;

    // ldmatrix lane components
    const int j   = lane >> 3;
    const int l7  = lane & 7;
    const int aLr = (j & 1) * 8 + l7;   // A-style (Q/P) row
    const int aLc = (j >> 1) * 8;
    const int nLr = (j >> 1) * 8 + l7;  // K non-trans n-row
    const int nLc = (j & 1) * 8;
    const int vLk = (j & 1) * 8 + l7;   // V trans key-row
    const int vLn = (j >> 1) * 8;

    auto issue_q = [&]() {
        const __half* src = qkv + ((size_t)(b * SEQ + q0 + qRow)) * (3 * DMODEL)
                          + h * HD;
        uint32_t qd = p_u32 + (uint32_t)(qRow * AT_S) * 2;
        #pragma unroll
        for (int i = 0; i < 4; i++)
            cp_async16(qd + (qC0 + i) * 16, src + (qC0 + i) * 8);
        cp_commit();
    };
    auto issue_kv = [&](int kt, int s) {
        const __half* src = qkv + ((size_t)(b * SEQ + kt + sRow)) * (3 * DMODEL)
                          + DMODEL + h * HD;
        uint32_t kd = k_u32 + (uint32_t)(s * KV_STGH + sRow * AT_S) * 2;
        uint32_t vd = v_u32 + (uint32_t)(s * KV_STGH + sRow * AT_S) * 2;
        #pragma unroll
        for (int i = 0; i < 2; i++) {
            cp_async16(kd + (sC0 + i) * 16, src + (sC0 + i) * 8);
            cp_async16(vd + (sC0 + i) * 16, src + DMODEL + (sC0 + i) * 8);
        }
        cp_commit();
    };

    issue_q();
    issue_kv(0, 0);
    cp_wait<0>();
    __syncthreads();

    // Q fragments resident (4 k16 slabs)
    uint32_t qa[4][4];
    #pragma unroll
    for (int sl = 0; sl < 4; sl++) {
        uint32_t ad = p_u32 +
            (uint32_t)((wid * 16 + aLr) * AT_S + sl * 16 + aLc) * 2;
        ldsm4(qa[sl][0], qa[sl][1], qa[sl][2], qa[sl][3], ad);
    }

    float o[8][4];
    #pragma unroll
    for (int n = 0; n < 8; n++)
        #pragma unroll
        for (int q = 0; q < 4; q++) o[n][q] = 0.0f;
    float m0 = -1e30f, m1 = -1e30f, l0 = 0.0f, l1 = 0.0f;

    const int NT = SEQ / 64;
    for (int t = 0; t < NT; t++) {
        if (t > 0) {
            cp_wait<0>();
            __syncthreads();
        }
        if (t + 1 < NT) issue_kv((t + 1) * 64, (t + 1) & 1);

        const uint32_t kb = k_u32 + (uint32_t)((t & 1) * KV_STGH) * 2;
        const uint32_t vb = v_u32 + (uint32_t)((t & 1) * KV_STGH) * 2;

        // ---- S = Q K^T ----
        float s[8][4];
        #pragma unroll
        for (int n = 0; n < 8; n++)
            #pragma unroll
            for (int q = 0; q < 4; q++) s[n][q] = 0.0f;
        #pragma unroll
        for (int sl = 0; sl < 4; sl++) {
            const int kk = sl * 16;
            #pragma unroll
            for (int g = 0; g < 4; g++) {
                uint32_t r0, r1, r2, r3;
                uint32_t kd = kb + (uint32_t)((g * 16 + nLr) * AT_S + kk + nLc) * 2;
                ldsm4(r0, r1, r2, r3, kd);
                mma16(s[2 * g],     qa[sl], r0, r1);
                mma16(s[2 * g + 1], qa[sl], r2, r3);
            }
        }

        // ---- online softmax (base-2, f16x2 exp), rows pr and pr+8 ----
        float mx0 = -1e30f, mx1 = -1e30f;
        #pragma unroll
        for (int n = 0; n < 8; n++) {
            s[n][0] *= SCALE_LOG2E; s[n][1] *= SCALE_LOG2E;
            s[n][2] *= SCALE_LOG2E; s[n][3] *= SCALE_LOG2E;
            mx0 = fmaxf(mx0, fmaxf(s[n][0], s[n][1]));
            mx1 = fmaxf(mx1, fmaxf(s[n][2], s[n][3]));
        }
        mx0 = fmaxf(mx0, __shfl_xor_sync(0xffffffffu, mx0, 1));
        mx0 = fmaxf(mx0, __shfl_xor_sync(0xffffffffu, mx0, 2));
        mx1 = fmaxf(mx1, __shfl_xor_sync(0xffffffffu, mx1, 1));
        mx1 = fmaxf(mx1, __shfl_xor_sync(0xffffffffu, mx1, 2));
        const float mn0 = fmaxf(m0, mx0);
        const float mn1 = fmaxf(m1, mx1);
        const float al0 = fast_ex2(m0 - mn0);
        const float al1 = fast_ex2(m1 - mn1);
        m0 = mn0; m1 = mn1;

        // exp2 in packed fp16; result IS fp16 P -> store directly
        float sum0 = 0.0f, sum1 = 0.0f;
        #pragma unroll
        for (int n = 0; n < 8; n++) {
            uint32_t p0 = ex2_h2(s[n][0] - mn0, s[n][1] - mn0);
            uint32_t p1 = ex2_h2(s[n][2] - mn1, s[n][3] - mn1);
            *(uint32_t*)&Pq[(pr    ) * AT_S + n * 8 + 2 * tig] = p0;
            *(uint32_t*)&Pq[(pr + 8) * AT_S + n * 8 + 2 * tig] = p1;
            float2 f0 = __half22float2(*reinterpret_cast<__half2*>(&p0));
            float2 f1 = __half22float2(*reinterpret_cast<__half2*>(&p1));
            sum0 += f0.x + f0.y;
            sum1 += f1.x + f1.y;
        }
        sum0 += __shfl_xor_sync(0xffffffffu, sum0, 1);
        sum0 += __shfl_xor_sync(0xffffffffu, sum0, 2);
        sum1 += __shfl_xor_sync(0xffffffffu, sum1, 1);
        sum1 += __shfl_xor_sync(0xffffffffu, sum1, 2);
        l0 = l0 * al0 + sum0;
        l1 = l1 * al1 + sum1;

        #pragma unroll
        for (int n = 0; n < 8; n++) {
            o[n][0] *= al0; o[n][1] *= al0;
            o[n][2] *= al1; o[n][3] *= al1;
        }
        __syncwarp();

        // ---- O += P @ V ----
        #pragma unroll
        for (int sl = 0; sl < 4; sl++) {
            const int kk = sl * 16;
            uint32_t pa[4];
            {
                uint32_t pd = p_u32 +
                    (uint32_t)((wid * 16 + aLr) * AT_S + kk + aLc) * 2;
                ldsm4(pa[0], pa[1], pa[2], pa[3], pd);
            }
            #pragma unroll
            for (int g = 0; g < 4; g++) {
                uint32_t r0, r1, r2, r3;
                uint32_t vd = vb + (uint32_t)((kk + vLk) * AT_S + g * 16 + vLn) * 2;
                ldsm4t(r0, r1, r2, r3, vd);
                mma16(o[2 * g],     pa, r0, r1);
                mma16(o[2 * g + 1], pa, r2, r3);
            }
        }
    }

    // ---- normalize + write y (fp16) ----
    const float i0 = 1.0f / l0;
    const float i1 = 1.0f / l1;
    __half* yp = y + ((size_t)(b * SEQ + q0 + pr)) * DMODEL + h * HD;
    #pragma unroll
    for (int n = 0; n < 8; n++) {
        const int cc = n * 8 + 2 * tig;
        *(__half2*)&yp[cc] = __floats2half2_rn(o[n][0] * i0, o[n][1] * i0);
        *(__half2*)&yp[8 * DMODEL + cc] =
            __floats2half2_rn(o[n][2] * i1, o[n][3] * i1);
    }
}

// ---------------------------------------------------------------------------
// Launch
// ---------------------------------------------------------------------------
extern "C" void kernel_launch(void* const* d_in, const int* in_sizes, int n_in,
                              void* d_out, int out_size)
{
    const float* x     = (const float*)d_in[0];
    const float* Wqkv  = (const float*)d_in[1];
    const float* bqkv  = (const float*)d_in[2];
    const float* Wproj = (const float*)d_in[3];
    const float* bproj = (const float*)d_in[4];
    float* out = (float*)d_out;

    __half *qkv = nullptr, *y = nullptr, *xh = nullptr, *wq = nullptr, *wp = nullptr;
    cudaGetSymbolAddress((void**)&qkv, g_qkv);
    cudaGetSymbolAddress((void**)&y,   g_y);
    cudaGetSymbolAddress((void**)&xh,  g_x);
    cudaGetSymbolAddress((void**)&wq,  g_wq);
    cudaGetSymbolAddress((void**)&wp,  g_wp);

    cudaFuncSetAttribute(gemm_fp16<true>,
                         cudaFuncAttributeMaxDynamicSharedMemorySize, GEMM_SMEM);
    cudaFuncSetAttribute(gemm_fp16<false>,
                         cudaFuncAttributeMaxDynamicSharedMemorySize, GEMM_SMEM);
    cudaFuncSetAttribute(attn_fp16,
                         cudaFuncAttributeMaxDynamicSharedMemorySize, ATTN_SMEM);

    // 0) convert inputs/weights to fp16 (single fused launch)
    {
        const int na4 = MTOT * DMODEL / 4;           // x
        const int nb4 = DMODEL * 3 * DMODEL / 4;     // Wqkv
        const int nc4 = DMODEL * DMODEL / 4;         // Wproj
        const int tot = na4 + nb4 + nc4;
        to_half3<<<(tot + 255) / 256, 256>>>(x, xh, na4, Wqkv, wq, nb4,
                                             Wproj, wp, nc4);
    }

    // 1) QKV projection -> fp16 qkv
    gemm_fp16<true><<<dim3(3 * DMODEL / 128, MTOT / 128), 256, GEMM_SMEM>>>(
        MTOT, 3 * DMODEL, DMODEL, xh, wq, bqkv, qkv);

    // 2) flash attention -> fp16 y  (256 threads, Br=128)
    attn_fp16<<<dim3(SEQ / 128, NHEAD, BATCH), 256, ATTN_SMEM>>>(qkv, y);

    // 3) output projection -> fp32 out
    gemm_fp16<false><<<dim3(DMODEL / 128, MTOT / 128), 256, GEMM_SMEM>>>(
        MTOT, DMODEL, DMODEL, y, wp, bproj, out);
}